// round 1
// baseline (speedup 1.0000x reference)
#include <cuda_runtime.h>
#include <cuda_bf16.h>
#include <math.h>

// Problem constants
#define BATCH 256
#define Hh 26
#define Ww 26
#define HW (Hh * Ww)          // 676
#define A_NUM 5
#define NCLS 20
#define CPA 25                 // channels per anchor (20 cls, conf, xy, wh)
#define CH (A_NUM * CPA)       // 125
#define TOTAL (BATCH * HW)     // 173056

__device__ __constant__ float c_aw[5] = {1.3221f, 3.19275f, 5.05587f, 9.47112f, 11.2364f};
__device__ __constant__ float c_ah[5] = {1.73145f, 4.00944f, 8.09892f, 4.84053f, 10.0071f};

__device__ __forceinline__ float sigmoidf_acc(float x) {
    return 1.0f / (1.0f + expf(-x));
}

__global__ void __launch_bounds__(256) yolo_loss_kernel(
    const float* __restrict__ pred,   // (B, 125, 26, 26)
    const float* __restrict__ tgt,    // (B, 26, 26, 25)
    float* __restrict__ out)          // 4 floats: box, conf, noobj, cls
{
    int i = blockIdx.x * blockDim.x + threadIdx.x;

    float box_l = 0.f, conf_l = 0.f, noobj_l = 0.f, cls_l = 0.f;

    if (i < TOTAL) {
        int b = i / HW;
        int hw = i - b * HW;
        const float* __restrict__ pbase = pred + (size_t)b * CH * HW + hw;
        const float* __restrict__ t = tgt + (size_t)i * CPA;

        // target box + conf (offsets 20..24 only — skip the one-hot unless obj)
        float gconf = t[20];
        float gx = t[21], gy = t[22], gw = t[23], gh = t[24];

        float gx1 = gx - 0.5f * gw, gy1 = gy - 0.5f * gh;
        float gx2 = gx + 0.5f * gw, gy2 = gy + 0.5f * gh;
        float garea = gw * gh;

        float best_iou = -1.0f;
        int   best_a   = 0;
        float bpx = 0.f, bpy = 0.f, bpw = 0.f, bph = 0.f, bconf = 0.f;

        #pragma unroll
        for (int a = 0; a < A_NUM; a++) {
            // 5 coalesced plane loads per anchor
            float tc = pbase[(a * CPA + 20) * HW];
            float tx = pbase[(a * CPA + 21) * HW];
            float ty = pbase[(a * CPA + 22) * HW];
            float tw = pbase[(a * CPA + 23) * HW];
            float th = pbase[(a * CPA + 24) * HW];

            float pc = sigmoidf_acc(tc);
            float px = sigmoidf_acc(tx);
            float py = sigmoidf_acc(ty);
            float pw = expf(tw) * c_aw[a];
            float ph = expf(th) * c_ah[a];

            // IoU with gt box
            float ax1 = px - 0.5f * pw, ay1 = py - 0.5f * ph;
            float ax2 = px + 0.5f * pw, ay2 = py + 0.5f * ph;
            float iw = fminf(ax2, gx2) - fmaxf(ax1, gx1);
            float ih = fminf(ay2, gy2) - fmaxf(ay1, gy1);
            iw = fmaxf(iw, 0.0f);
            ih = fmaxf(ih, 0.0f);
            float inter = iw * ih;
            float uni = pw * ph + garea - inter;
            float iou = inter / (uni + 1e-10f);

            // first-max argmax (strict >)
            if (iou > best_iou) {
                best_iou = iou;
                best_a = a;
                bpx = px; bpy = py; bpw = pw; bph = ph; bconf = pc;
            }
        }

        bool obj = (gconf != 0.0f);
        if (obj) {
            float dx = bpx - gx, dy = bpy - gy, dw = bpw - gw, dh = bph - gh;
            box_l  = dx * dx + dy * dy + dw * dw + dh * dh;
            float dc = bconf - gconf;
            conf_l = dc * dc;

            // class loss: gather 20 logits of best anchor + target one-hot
            const float* __restrict__ lb = pbase + (size_t)(best_a * CPA) * HW;
            float m = -INFINITY;
            float logits[NCLS];
            #pragma unroll
            for (int c = 0; c < NCLS; c++) {
                float v = lb[c * HW];
                logits[c] = v;
                m = fmaxf(m, v);
            }
            float s = 0.f;
            #pragma unroll
            for (int c = 0; c < NCLS; c++) s += expf(logits[c] - m);
            float lse = m + logf(s);

            // label = argmax of one-hot (first max)
            int label = 0;
            float bestv = t[0];
            #pragma unroll
            for (int c = 1; c < NCLS; c++) {
                float v = t[c];
                if (v > bestv) { bestv = v; label = c; }
            }
            cls_l = lse - logits[label];   // -logp[label]
        } else {
            noobj_l = bconf * bconf;
        }
    }

    // warp reduce
    #pragma unroll
    for (int off = 16; off > 0; off >>= 1) {
        box_l   += __shfl_down_sync(0xFFFFFFFFu, box_l,   off);
        conf_l  += __shfl_down_sync(0xFFFFFFFFu, conf_l,  off);
        noobj_l += __shfl_down_sync(0xFFFFFFFFu, noobj_l, off);
        cls_l   += __shfl_down_sync(0xFFFFFFFFu, cls_l,   off);
    }

    __shared__ float sm[4][8];
    int lane = threadIdx.x & 31;
    int wid  = threadIdx.x >> 5;
    if (lane == 0) {
        sm[0][wid] = box_l;
        sm[1][wid] = conf_l;
        sm[2][wid] = noobj_l;
        sm[3][wid] = cls_l;
    }
    __syncthreads();
    if (wid == 0) {
        int nw = blockDim.x >> 5;
        float v0 = (lane < nw) ? sm[0][lane] : 0.f;
        float v1 = (lane < nw) ? sm[1][lane] : 0.f;
        float v2 = (lane < nw) ? sm[2][lane] : 0.f;
        float v3 = (lane < nw) ? sm[3][lane] : 0.f;
        #pragma unroll
        for (int off = 4; off > 0; off >>= 1) {
            v0 += __shfl_down_sync(0xFFFFFFFFu, v0, off);
            v1 += __shfl_down_sync(0xFFFFFFFFu, v1, off);
            v2 += __shfl_down_sync(0xFFFFFFFFu, v2, off);
            v3 += __shfl_down_sync(0xFFFFFFFFu, v3, off);
        }
        if (lane == 0) {
            const float inv_b = 1.0f / (float)BATCH;
            atomicAdd(out + 0, v0 * (5.0f * inv_b));   // LAMBDA_COORD
            atomicAdd(out + 1, v1 * (1.0f * inv_b));   // LAMBDA_OBJ
            atomicAdd(out + 2, v2 * (0.5f * inv_b));   // LAMBDA_NOOBJ
            atomicAdd(out + 3, v3 * (1.0f * inv_b));   // LAMBDA_CLS
        }
    }
}

extern "C" void kernel_launch(void* const* d_in, const int* in_sizes, int n_in,
                              void* d_out, int out_size) {
    const float* pred = (const float*)d_in[0];
    const float* tgt  = (const float*)d_in[1];
    float* out = (float*)d_out;

    cudaMemsetAsync(out, 0, 4 * sizeof(float), 0);

    int threads = 256;
    int blocks = (TOTAL + threads - 1) / threads;   // 676
    yolo_loss_kernel<<<blocks, threads>>>(pred, tgt, out);
}

// round 2
// speedup vs baseline: 1.3256x; 1.3256x over previous
#include <cuda_runtime.h>
#include <cuda_bf16.h>
#include <math.h>

// Problem constants
#define BATCH 256
#define Hh 26
#define Ww 26
#define HW (Hh * Ww)          // 676
#define A_NUM 5
#define NCLS 20
#define CPA 25                 // channels per anchor (20 cls, conf, xy, wh)
#define CH (A_NUM * CPA)       // 125
#define TOTAL (BATCH * HW)     // 173056
#define NBLOCKS 740            // 5 * 148 SMs — perfectly balanced wave

__device__ __constant__ float c_aw[5] = {1.3221f, 3.19275f, 5.05587f, 9.47112f, 11.2364f};
__device__ __constant__ float c_ah[5] = {1.73145f, 4.00944f, 8.09892f, 4.84053f, 10.0071f};

// fast sigmoid: MUFU.EX2 + MUFU.RCP (error ~2^-22, vastly inside 1e-3 budget)
__device__ __forceinline__ float fsigmoid(float x) {
    return __fdividef(1.0f, 1.0f + __expf(-x));
}

__global__ void __launch_bounds__(256, 5) yolo_loss_kernel(
    const float* __restrict__ pred,   // (B, 125, 26, 26)
    const float* __restrict__ tgt,    // (B, 26, 26, 25)
    float* __restrict__ out)          // 4 floats: box, conf, noobj, cls
{
    int i = blockIdx.x * blockDim.x + threadIdx.x;

    float box_l = 0.f, conf_l = 0.f, noobj_l = 0.f, cls_l = 0.f;

    if (i < TOTAL) {
        int b = i / HW;
        int hw = i - b * HW;
        const float* __restrict__ pbase = pred + (size_t)b * CH * HW + hw;
        const float* __restrict__ t = tgt + (size_t)i * CPA;

        // ---- front-batch ALL pred loads (25 independent LDGs, one DRAM round trip)
        float p[A_NUM * 5];
        #pragma unroll
        for (int a = 0; a < A_NUM; a++) {
            #pragma unroll
            for (int j = 0; j < 5; j++) {
                p[a * 5 + j] = __ldg(&pbase[(a * CPA + 20 + j) * HW]);
            }
        }

        // target box + conf (offsets 20..24 only)
        float gconf = __ldg(&t[20]);
        float gx = __ldg(&t[21]), gy = __ldg(&t[22]);
        float gw = __ldg(&t[23]), gh = __ldg(&t[24]);

        float gx1 = gx - 0.5f * gw, gy1 = gy - 0.5f * gh;
        float gx2 = gx + 0.5f * gw, gy2 = gy + 0.5f * gh;
        float garea = gw * gh;

        float best_iou = -1.0f;
        int   best_a   = 0;
        float bpx = 0.f, bpy = 0.f, bpw = 0.f, bph = 0.f, bconf = 0.f;

        #pragma unroll
        for (int a = 0; a < A_NUM; a++) {
            float pc = fsigmoid(p[a * 5 + 0]);
            float px = fsigmoid(p[a * 5 + 1]);
            float py = fsigmoid(p[a * 5 + 2]);
            float pw = __expf(p[a * 5 + 3]) * c_aw[a];
            float ph = __expf(p[a * 5 + 4]) * c_ah[a];

            float ax1 = px - 0.5f * pw, ay1 = py - 0.5f * ph;
            float ax2 = px + 0.5f * pw, ay2 = py + 0.5f * ph;
            float iw = fmaxf(fminf(ax2, gx2) - fmaxf(ax1, gx1), 0.0f);
            float ih = fmaxf(fminf(ay2, gy2) - fmaxf(ay1, gy1), 0.0f);
            float inter = iw * ih;
            float uni = pw * ph + garea - inter;
            float iou = __fdividef(inter, uni + 1e-10f);

            if (iou > best_iou) {       // first-max argmax (strict >)
                best_iou = iou;
                best_a = a;
                bpx = px; bpy = py; bpw = pw; bph = ph; bconf = pc;
            }
        }

        bool obj = (gconf != 0.0f);
        if (obj) {
            float dx = bpx - gx, dy = bpy - gy, dw = bpw - gw, dh = bph - gh;
            box_l  = dx * dx + dy * dy + dw * dw + dh * dh;
            float dc = bconf - gconf;
            conf_l = dc * dc;

            // class loss: gather 20 logits of best anchor
            const float* __restrict__ lb = pbase + (size_t)(best_a * CPA) * HW;
            float logits[NCLS];
            float m = -INFINITY;
            #pragma unroll
            for (int c = 0; c < NCLS; c++) {
                float v = __ldg(&lb[c * HW]);
                logits[c] = v;
                m = fmaxf(m, v);
            }
            float s = 0.f;
            #pragma unroll
            for (int c = 0; c < NCLS; c++) s += __expf(logits[c] - m);
            float lse = m + __logf(s);

            // label = argmax of one-hot (values exactly 0/1 — exact compare)
            int label = 0;
            float bestv = __ldg(&t[0]);
            #pragma unroll
            for (int c = 1; c < NCLS; c++) {
                float v = __ldg(&t[c]);
                if (v > bestv) { bestv = v; label = c; }
            }
            cls_l = lse - logits[label];   // -logp[label]
        } else {
            noobj_l = bconf * bconf;
        }
    }

    // warp reduce
    #pragma unroll
    for (int off = 16; off > 0; off >>= 1) {
        box_l   += __shfl_down_sync(0xFFFFFFFFu, box_l,   off);
        conf_l  += __shfl_down_sync(0xFFFFFFFFu, conf_l,  off);
        noobj_l += __shfl_down_sync(0xFFFFFFFFu, noobj_l, off);
        cls_l   += __shfl_down_sync(0xFFFFFFFFu, cls_l,   off);
    }

    __shared__ float sm[4][8];
    int lane = threadIdx.x & 31;
    int wid  = threadIdx.x >> 5;
    if (lane == 0) {
        sm[0][wid] = box_l;
        sm[1][wid] = conf_l;
        sm[2][wid] = noobj_l;
        sm[3][wid] = cls_l;
    }
    __syncthreads();
    if (wid == 0) {
        float v0 = (lane < 8) ? sm[0][lane] : 0.f;
        float v1 = (lane < 8) ? sm[1][lane] : 0.f;
        float v2 = (lane < 8) ? sm[2][lane] : 0.f;
        float v3 = (lane < 8) ? sm[3][lane] : 0.f;
        #pragma unroll
        for (int off = 4; off > 0; off >>= 1) {
            v0 += __shfl_down_sync(0xFFFFFFFFu, v0, off);
            v1 += __shfl_down_sync(0xFFFFFFFFu, v1, off);
            v2 += __shfl_down_sync(0xFFFFFFFFu, v2, off);
            v3 += __shfl_down_sync(0xFFFFFFFFu, v3, off);
        }
        if (lane == 0) {
            const float inv_b = 1.0f / (float)BATCH;
            atomicAdd(out + 0, v0 * (5.0f * inv_b));   // LAMBDA_COORD
            atomicAdd(out + 1, v1 * (1.0f * inv_b));   // LAMBDA_OBJ
            atomicAdd(out + 2, v2 * (0.5f * inv_b));   // LAMBDA_NOOBJ
            atomicAdd(out + 3, v3 * (1.0f * inv_b));   // LAMBDA_CLS
        }
    }
}

extern "C" void kernel_launch(void* const* d_in, const int* in_sizes, int n_in,
                              void* d_out, int out_size) {
    const float* pred = (const float*)d_in[0];
    const float* tgt  = (const float*)d_in[1];
    float* out = (float*)d_out;

    cudaMemsetAsync(out, 0, 4 * sizeof(float), 0);

    yolo_loss_kernel<<<NBLOCKS, 256>>>(pred, tgt, out);
}